// round 14
// baseline (speedup 1.0000x reference)
#include <cuda_runtime.h>
#include <math.h>

#define Nn 50000
#define Ee 500000
#define Gg 32
#define Hh 4
#define Dd 40
#define HID 160
#define JK 320
#define NBLK 196   // ceil(Nn/256)

// ---------------- scratch ----------------
__device__ float    g_h0[(size_t)Nn*HID];
__device__ float    g_q[(size_t)Nn*HID];
__device__ float    g_k[(size_t)Nn*HID];
__device__ float    g_v[(size_t)Nn*HID];
__device__ float    g_skip[(size_t)Nn*HID];
__device__ float    g_out[(size_t)Nn*HID];
__device__ float    g_xc[(size_t)Nn*JK];
__device__ float    g_xct[(size_t)Nn*JK];        // tf32-rounded copy for GEMM A
__device__ float    g_alpha[(size_t)Ee*Hh];      // slot-indexed
__device__ float    g_gate[Nn];
__device__ unsigned g_gmax[Gg];
__device__ float    g_gden[Gg];
__device__ float    g_pooled[Gg*JK];
__device__ int      g_ei32[(size_t)2*Ee];
__device__ int      g_batch32[Nn];
__device__ int      g_is64;
__device__ int      g_cnt[Nn];
__device__ int      g_rowptr[Nn+1];
__device__ int      g_fill[Nn];
__device__ int      g_srcs[Ee];                  // slot-ordered src node
__device__ int      g_dsts[Ee];                  // slot-ordered dst node
__device__ float4   g_eap[Ee];                   // slot-ordered edge attrs
__device__ int      g_bsum[NBLK];
__device__ int      g_boff[NBLK];
// tf32-rounded weights
__device__ float    g_wq[2*HID*HID];
__device__ float    g_wk[2*HID*HID];
__device__ float    g_wv[2*HID*HID];
__device__ float    g_ws[2*HID*HID];
__device__ float    g_wg1[JK*HID];

__device__ __forceinline__ unsigned fenc(float f){
    unsigned u = __float_as_uint(f);
    return (u & 0x80000000u) ? ~u : (u | 0x80000000u);
}
__device__ __forceinline__ float fdec(unsigned e){
    return (e & 0x80000000u) ? __uint_as_float(e ^ 0x80000000u) : __uint_as_float(~e);
}
__device__ __forceinline__ float rna_tf32(float f){
    unsigned u;
    asm("cvt.rna.tf32.f32 %0, %1;" : "=r"(u) : "f"(f));
    return __uint_as_float(u);
}

// ---------------- dtype detection + index normalization ----------------
__global__ void k_detect(const void* __restrict__ ei){
    const long long* p = (const long long*)ei;
    int bad = 0;
    for (int i = threadIdx.x; i < 4096; i += 256){
        long long v = p[i];
        if (v < 0 || v >= Nn) bad = 1;
    }
    bad = __syncthreads_or(bad);
    if (threadIdx.x == 0) g_is64 = bad ? 0 : 1;
}

__global__ void k_convert(const void* __restrict__ ei, const void* __restrict__ batch){
    int idx = blockIdx.x*blockDim.x + threadIdx.x;
    int is64 = g_is64;
    if (idx < 2*Ee){
        g_ei32[idx] = is64 ? (int)((const long long*)ei)[idx]
                           : ((const int*)ei)[idx];
    }
    if (idx < Nn){
        g_batch32[idx] = is64 ? (int)((const long long*)batch)[idx]
                              : ((const int*)batch)[idx];
        g_cnt[idx] = 0;
    }
}

// ---------------- weight rounding ----------------
__global__ void k_cvtw(const float* __restrict__ Wq, const float* __restrict__ Wk,
                       const float* __restrict__ Wv, const float* __restrict__ Ws,
                       const float* __restrict__ Wg1){
    int i = blockIdx.x*blockDim.x + threadIdx.x;
    const int n1 = 2*HID*HID;
    if (i < n1)            g_wq[i]        = rna_tf32(Wq[i]);
    else if (i < 2*n1)     g_wk[i-n1]     = rna_tf32(Wk[i-n1]);
    else if (i < 3*n1)     g_wv[i-2*n1]   = rna_tf32(Wv[i-2*n1]);
    else if (i < 4*n1)     g_ws[i-3*n1]   = rna_tf32(Ws[i-3*n1]);
    else if (i < 4*n1 + JK*HID) g_wg1[i-4*n1] = rna_tf32(Wg1[i-4*n1]);
}

// ---------------- CSR build ----------------
__global__ void k_count(){
    int e = blockIdx.x*blockDim.x + threadIdx.x;
    if (e < Ee) atomicAdd(&g_cnt[g_ei32[Ee + e]], 1);
}

__global__ __launch_bounds__(256) void k_scan1(){
    __shared__ int s[256];
    int t = threadIdx.x;
    int idx = blockIdx.x*256 + t;
    int v = (idx < Nn) ? g_cnt[idx] : 0;
    s[t] = v; __syncthreads();
#pragma unroll
    for (int off = 1; off < 256; off <<= 1){
        int x = (t >= off) ? s[t-off] : 0;
        __syncthreads();
        s[t] += x;
        __syncthreads();
    }
    if (idx < Nn) g_rowptr[idx] = s[t] - v;
    if (t == 255) g_bsum[blockIdx.x] = s[255];
}

__global__ __launch_bounds__(256) void k_scan2(){
    __shared__ int s[256];
    int t = threadIdx.x;
    int v = (t < NBLK) ? g_bsum[t] : 0;
    s[t] = v; __syncthreads();
#pragma unroll
    for (int off = 1; off < 256; off <<= 1){
        int x = (t >= off) ? s[t-off] : 0;
        __syncthreads();
        s[t] += x;
        __syncthreads();
    }
    if (t < NBLK) g_boff[t] = s[t] - v;
}

__global__ void k_scan3(){
    int idx = blockIdx.x*blockDim.x + threadIdx.x;
    if (idx < Nn){
        int r = g_rowptr[idx] + g_boff[idx >> 8];
        g_rowptr[idx] = r;
        g_fill[idx] = r;
    }
    if (idx == 0) g_rowptr[Nn] = Ee;
}

// fill slot-ordered edge arrays (src, dst, edge attrs)
__global__ void k_fill(const float* __restrict__ ea){
    int e = blockIdx.x*blockDim.x + threadIdx.x;
    if (e < Ee){
        int src = g_ei32[e];
        int dst = g_ei32[Ee + e];
        int slot = atomicAdd(&g_fill[dst], 1);
        g_srcs[slot] = src;
        g_dsts[slot] = dst;
        g_eap[slot]  = reinterpret_cast<const float4*>(ea)[e];
    }
}

// ---------------- input projection ----------------
__global__ __launch_bounds__(HID) void k_input(const float* __restrict__ x,
                                               const float* __restrict__ W,
                                               const float* __restrict__ b){
    int n = blockIdx.x, c = threadIdx.x;
    __shared__ float xr[5];
    if (c < 5) xr[c] = x[n*5 + c];
    __syncthreads();
    float acc = b[c];
#pragma unroll
    for (int j = 0; j < 5; j++) acc = fmaf(xr[j], W[j*HID + c], acc);
    g_h0[(size_t)n*HID + c] = rna_tf32(acc);
}

// ---------------- TF32 tensor-core GEMM, cp.async double-buffered -------------
#define SA_STR 36
#define SB_STR 136
#define SMEM_GEMM ((2*128*SA_STR + 2*32*SB_STR)*4)

#define STAGE(buf_, k0_) do{ \
    _Pragma("unroll") \
    for (int r_ = 0; r_ < 4; r_++){ \
        int s_ = tid + 256*r_; \
        int row_ = s_ >> 3, c4_ = (s_ & 7) << 2; \
        const float* src_ = A + (size_t)(bm+row_)*lda + (k0_) + c4_; \
        int sz_ = (bm + row_ < M) ? 16 : 0; \
        if (!sz_) src_ = A; \
        unsigned da_ = sbase + (unsigned)(((buf_)*128*SA_STR + row_*SA_STR + c4_)*4); \
        asm volatile("cp.async.cg.shared.global [%0], [%1], 16, %2;" \
                     :: "r"(da_), "l"(src_), "r"(sz_)); \
    } \
    _Pragma("unroll") \
    for (int r_ = 0; r_ < 4; r_++){ \
        int kr_ = (tid >> 5) + 8*r_; \
        const float* src_ = Bm ? (Bm + (size_t)((k0_)+kr_)*matcols + bc2) : A; \
        int sz_ = Bm ? 16 : 0; \
        unsigned db_ = sbbase + (unsigned)(((buf_)*32*SB_STR + kr_*SB_STR + nc)*4); \
        asm volatile("cp.async.cg.shared.global [%0], [%1], 16, %2;" \
                     :: "r"(db_), "l"(src_), "r"(sz_)); \
    } \
    asm volatile("cp.async.commit_group;"); \
}while(0)

__global__ __launch_bounds__(256,2) void k_gemm_tf32(
    const float* __restrict__ A, int lda, int M, int K,
    const float* __restrict__ B0, const float* __restrict__ B1,
    const float* __restrict__ B2, const float* __restrict__ B3,
    const float* __restrict__ bias0, const float* __restrict__ bias1,
    const float* __restrict__ bias2, const float* __restrict__ bias3,
    int matcols, int Ntot,
    float* __restrict__ C0, float* __restrict__ C1,
    float* __restrict__ C2, float* __restrict__ C3, int relu)
{
    extern __shared__ float smem[];
    float* sA = smem;
    float* sB = smem + 2*128*SA_STR;
    int tid = threadIdx.x;
    int bm = blockIdx.y*128, bn = blockIdx.x*128;
    int warp = tid >> 5, lane = tid & 31;
    int wm = (warp & 1)*64, wn = (warp >> 1)*32;
    int g = lane >> 2, l4 = lane & 3;

    unsigned sbase  = (unsigned)__cvta_generic_to_shared(sA);
    unsigned sbbase = (unsigned)__cvta_generic_to_shared(sB);

    int nc = (tid & 31) << 2;
    int col_st = bn + nc;
    const float* Bm = nullptr; int bc2 = 0;
    if (col_st < Ntot){
        int m = col_st / matcols;
        bc2 = col_st - m*matcols;
        Bm = (m==0)?B0:(m==1)?B1:(m==2)?B2:B3;
    }

    float acc[4][4][4];
#pragma unroll
    for (int i = 0; i < 4; i++)
#pragma unroll
        for (int j = 0; j < 4; j++)
#pragma unroll
            for (int r = 0; r < 4; r++) acc[i][j][r] = 0.f;

    STAGE(0, 0);
    int nt = K >> 5;
    for (int t = 0; t < nt; t++){
        int buf = t & 1;
        if (t+1 < nt){
            STAGE(buf^1, (t+1)*32);
            asm volatile("cp.async.wait_group 1;");
        } else {
            asm volatile("cp.async.wait_group 0;");
        }
        __syncthreads();

        const unsigned* uA = reinterpret_cast<const unsigned*>(sA + buf*128*SA_STR);
        const unsigned* uB = reinterpret_cast<const unsigned*>(sB + buf*32*SB_STR);
#pragma unroll
        for (int k8 = 0; k8 < 4; k8++){
            unsigned a[4][4], b[4][2];
            int c0 = k8*8 + l4;
#pragma unroll
            for (int i = 0; i < 4; i++){
                int r0 = wm + i*16 + g;
                a[i][0] = uA[r0*SA_STR + c0];
                a[i][1] = uA[(r0+8)*SA_STR + c0];
                a[i][2] = uA[r0*SA_STR + c0 + 4];
                a[i][3] = uA[(r0+8)*SA_STR + c0 + 4];
            }
#pragma unroll
            for (int j = 0; j < 4; j++){
                int nn = wn + j*8 + g;
                b[j][0] = uB[(k8*8 + l4)*SB_STR + nn];
                b[j][1] = uB[(k8*8 + l4 + 4)*SB_STR + nn];
            }
#pragma unroll
            for (int i = 0; i < 4; i++)
#pragma unroll
                for (int j = 0; j < 4; j++){
                    asm volatile(
                        "mma.sync.aligned.m16n8k8.row.col.f32.tf32.tf32.f32 "
                        "{%0,%1,%2,%3}, {%4,%5,%6,%7}, {%8,%9}, {%0,%1,%2,%3};\n"
                        : "+f"(acc[i][j][0]), "+f"(acc[i][j][1]),
                          "+f"(acc[i][j][2]), "+f"(acc[i][j][3])
                        : "r"(a[i][0]), "r"(a[i][1]), "r"(a[i][2]), "r"(a[i][3]),
                          "r"(b[j][0]), "r"(b[j][1]));
                }
        }
        __syncthreads();
    }

#pragma unroll
    for (int j = 0; j < 4; j++){
        int col = bn + wn + j*8 + 2*l4;
        if (col >= Ntot) continue;
        int m  = col / matcols;
        int c2 = col - m*matcols;
        const float* bp = (m==0)?bias0:(m==1)?bias1:(m==2)?bias2:bias3;
        float*       Cm = (m==0)?C0:(m==1)?C1:(m==2)?C2:C3;
        float bx = bp[c2], by = bp[c2+1];
#pragma unroll
        for (int i = 0; i < 4; i++){
            int row0 = bm + wm + i*16 + g;
            float vx, vy;
            if (row0 < M){
                vx = acc[i][j][0] + bx; vy = acc[i][j][1] + by;
                if (relu){ vx = fmaxf(vx, 0.f); vy = fmaxf(vy, 0.f); }
                *reinterpret_cast<float2*>(Cm + (size_t)row0*matcols + c2) = make_float2(vx, vy);
            }
            int row1 = row0 + 8;
            if (row1 < M){
                vx = acc[i][j][2] + bx; vy = acc[i][j][3] + by;
                if (relu){ vx = fmaxf(vx, 0.f); vy = fmaxf(vy, 0.f); }
                *reinterpret_cast<float2*>(Cm + (size_t)row1*matcols + c2) = make_float2(vx, vy);
            }
        }
    }
}

// ---------------- edge: alpha logits over CSR slots (4 slots per warp) --------
__global__ __launch_bounds__(256) void k_edge_alpha(
    const float* __restrict__ We, const float* __restrict__ be)
{
    __shared__ float sWe[4*HID];
    __shared__ float sbe[HID];
    int t = threadIdx.x;
    for (int i = t; i < 4*HID; i += 256) sWe[i] = We[i];
    if (t < HID) sbe[t] = be[t];
    __syncthreads();
    int warp = t >> 5, lane = t & 31;
    int hh = lane >> 3, o = lane & 7;
    int cb = hh*Dd + o;
#pragma unroll
    for (int i4 = 0; i4 < 4; i4++){
        int s = blockIdx.x*32 + warp + 8*i4;
        int src = g_srcs[s];
        int dst = g_dsts[s];
        float4 ej = g_eap[s];
        const float* qr = g_q + (size_t)dst*HID;
        const float* kr = g_k + (size_t)src*HID;
        float part = 0.f;
#pragma unroll
        for (int i = 0; i < 5; i++){
            int c = cb + 8*i;
            float ev = sbe[c] + ej.x*sWe[c] + ej.y*sWe[HID+c] + ej.z*sWe[2*HID+c] + ej.w*sWe[3*HID+c];
            part = fmaf(qr[c], kr[c] + ev, part);
        }
        part += __shfl_down_sync(0xffffffffu, part, 4, 8);
        part += __shfl_down_sync(0xffffffffu, part, 2, 8);
        part += __shfl_down_sync(0xffffffffu, part, 1, 8);
        if (o == 0)
            g_alpha[(size_t)s*4 + hh] = part * 0.15811388300841897f;
    }
}

// ---------------- per-node softmax (contiguous alpha) ----------------
__global__ __launch_bounds__(256) void k_node_soft(){
    int t = threadIdx.x, warp = t >> 5, lane = t & 31;
    int n = blockIdx.x*8 + warp;
    int beg = g_rowptr[n], end = g_rowptr[n+1];
    int deg = end - beg;
    if (deg == 0) return;
    float4* al4 = reinterpret_cast<float4*>(g_alpha);

    float m0=-3.4e38f, m1=-3.4e38f, m2=-3.4e38f, m3=-3.4e38f;
    for (int i = lane; i < deg; i += 32){
        float4 a = al4[beg + i];
        m0 = fmaxf(m0, a.x); m1 = fmaxf(m1, a.y);
        m2 = fmaxf(m2, a.z); m3 = fmaxf(m3, a.w);
    }
#pragma unroll
    for (int off = 16; off; off >>= 1){
        m0 = fmaxf(m0, __shfl_xor_sync(0xffffffffu, m0, off));
        m1 = fmaxf(m1, __shfl_xor_sync(0xffffffffu, m1, off));
        m2 = fmaxf(m2, __shfl_xor_sync(0xffffffffu, m2, off));
        m3 = fmaxf(m3, __shfl_xor_sync(0xffffffffu, m3, off));
    }
    float s0=0.f, s1=0.f, s2=0.f, s3=0.f;
    for (int i = lane; i < deg; i += 32){
        float4 a = al4[beg + i];
        a.x = expf(a.x - m0); a.y = expf(a.y - m1);
        a.z = expf(a.z - m2); a.w = expf(a.w - m3);
        s0 += a.x; s1 += a.y; s2 += a.z; s3 += a.w;
        al4[beg + i] = a;
    }
#pragma unroll
    for (int off = 16; off; off >>= 1){
        s0 += __shfl_xor_sync(0xffffffffu, s0, off);
        s1 += __shfl_xor_sync(0xffffffffu, s1, off);
        s2 += __shfl_xor_sync(0xffffffffu, s2, off);
        s3 += __shfl_xor_sync(0xffffffffu, s3, off);
    }
    float r0 = 1.f/s0, r1 = 1.f/s1, r2 = 1.f/s2, r3 = 1.f/s3;
    for (int i = lane; i < deg; i += 32){
        float4 a = al4[beg + i];
        a.x *= r0; a.y *= r1; a.z *= r2; a.w *= r3;
        al4[beg + i] = a;
    }
}

// ---------------- per-node aggregation (8 nodes per block, contiguous staging) -
#define ECH 64
#define NPB 8
__global__ __launch_bounds__(HID) void k_node_aggr(
    const float* __restrict__ We, const float* __restrict__ be)
{
    __shared__ float sWe[4*HID];
    __shared__ float sbe[HID];
    __shared__ float4 s_ea[ECH];
    __shared__ float4 s_a[ECH];
    __shared__ int    s_src[ECH];
    int c = threadIdx.x;
    for (int i = c; i < 4*HID; i += HID) sWe[i] = We[i];
    sbe[c] = be[c];
    int h = c / Dd;
    const float4* al4 = reinterpret_cast<const float4*>(g_alpha);

    for (int nn = 0; nn < NPB; nn++){
        int n = blockIdx.x*NPB + nn;
        int beg = g_rowptr[n], end = g_rowptr[n+1];
        float acc = 0.f;
        for (int base = beg; base < end; base += ECH){
            int m = min(ECH, end - base);
            __syncthreads();
            if (c < m){
                s_src[c] = g_srcs[base + c];
                s_ea[c]  = g_eap[base + c];
                s_a[c]   = al4[base + c];
            }
            __syncthreads();
            for (int j = 0; j < m; j++){
                float4 ej = s_ea[j];
                float w = reinterpret_cast<const float*>(&s_a[j])[h];
                float ev = sbe[c] + ej.x*sWe[c] + ej.y*sWe[HID+c]
                         + ej.z*sWe[2*HID+c] + ej.w*sWe[3*HID+c];
                acc = fmaf(g_v[(size_t)s_src[j]*HID + c] + ev, w, acc);
            }
        }
        g_out[(size_t)n*HID + c] = acc;
    }
}

// ---------------- beta gate + combine (writes f32 xc + rounded xct) ----------
__global__ __launch_bounds__(256) void k_beta(const float* __restrict__ Wb, int l){
    int t = threadIdx.x, warp = t >> 5, lane = t & 31;
    int n = blockIdx.x*8 + warp;
    const float* o = g_out  + (size_t)n*HID;
    const float* r = g_skip + (size_t)n*HID;
    float oc[5], rc[5];
    float p = 0.f;
#pragma unroll
    for (int i = 0; i < 5; i++){
        int c = lane + 32*i;
        oc[i] = o[c]; rc[i] = r[c];
        p += oc[i]*Wb[c] + rc[i]*Wb[HID+c] + (oc[i]-rc[i])*Wb[2*HID+c];
    }
#pragma unroll
    for (int off = 16; off; off >>= 1) p += __shfl_xor_sync(0xffffffffu, p, off);
    float beta = 1.f/(1.f + expf(-p));
    float* hx  = g_xc  + (size_t)n*JK + (size_t)l*HID;
    float* hxt = g_xct + (size_t)n*JK + (size_t)l*HID;
#pragma unroll
    for (int i = 0; i < 5; i++){
        int c = lane + 32*i;
        float v = beta*rc[i] + (1.f - beta)*oc[i];
        hx[c]  = v;
        hxt[c] = rna_tf32(v);
    }
}

// ---------------- pooling ----------------
__global__ void k_init_pool(){
    int idx = blockIdx.x*blockDim.x + threadIdx.x;
    if (idx < Gg){ g_gmax[idx] = 0u; g_gden[idx] = 0.f; }
    if (idx < Gg*JK) g_pooled[idx] = 0.f;
}

__global__ __launch_bounds__(256) void k_gate(const float* __restrict__ Wg2,
                                              const float* __restrict__ bg2){
    int t = threadIdx.x, warp = t >> 5, lane = t & 31;
    int n = blockIdx.x*8 + warp;
    const float* tp = g_out + (size_t)n*HID;
    float p = 0.f;
#pragma unroll
    for (int i = 0; i < 5; i++){
        int c = lane + 32*i;
        p = fmaf(tp[c], Wg2[c], p);
    }
#pragma unroll
    for (int off = 16; off; off >>= 1) p += __shfl_xor_sync(0xffffffffu, p, off);
    if (lane == 0){
        float gate = p + bg2[0];
        g_gate[n] = gate;
        atomicMax(&g_gmax[g_batch32[n]], fenc(gate));
    }
}

__global__ void k_ge(){
    __shared__ float s[Gg];
    int t = threadIdx.x;
    if (t < Gg) s[t] = 0.f;
    __syncthreads();
    int n = blockIdx.x*blockDim.x + t;
    if (n < Nn){
        int b = g_batch32[n];
        float ge = expf(g_gate[n] - fdec(g_gmax[b]));
        g_gate[n] = ge;
        atomicAdd(&s[b], ge);
    }
    __syncthreads();
    if (t < Gg) atomicAdd(&g_gden[t], s[t]);
}

__global__ void k_att(){
    int n = blockIdx.x*blockDim.x + threadIdx.x;
    if (n < Nn) g_gate[n] /= g_gden[g_batch32[n]];
}

__global__ __launch_bounds__(JK) void k_pool(){
    int c = threadIdx.x;
    int n0 = blockIdx.x*128;
    if (n0 >= Nn) return;
    int nend = min(n0 + 128, Nn);
    int curg = g_batch32[n0];
    float acc = 0.f;
    for (int n = n0; n < nend; n++){
        int g = g_batch32[n];
        if (g != curg){
            atomicAdd(&g_pooled[curg*JK + c], acc);
            acc = 0.f; curg = g;
        }
        acc = fmaf(g_gate[n], g_xc[(size_t)n*JK + c], acc);
    }
    atomicAdd(&g_pooled[curg*JK + c], acc);
}

__global__ __launch_bounds__(JK) void k_final(const float* __restrict__ Wh1,
                                              const float* __restrict__ bh1,
                                              const float* __restrict__ Wh2,
                                              const float* __restrict__ bh2,
                                              float* __restrict__ outp){
    __shared__ float p[JK];
    __shared__ float t1[JK];
    int g = blockIdx.x, c = threadIdx.x;
    p[c] = g_pooled[g*JK + c];
    __syncthreads();
    float acc = bh1[c];
    for (int k = 0; k < JK; k++) acc = fmaf(p[k], Wh1[k*JK + c], acc);
    t1[c] = fmaxf(acc, 0.f);
    __syncthreads();
    int warp = c >> 5, lane = c & 31;
    if (warp < 6){
        float s = 0.f;
        for (int k = lane; k < JK; k += 32) s = fmaf(t1[k], Wh2[k*6 + warp], s);
#pragma unroll
        for (int off = 16; off; off >>= 1) s += __shfl_xor_sync(0xffffffffu, s, off);
        if (lane == 0) outp[g*6 + warp] = s + bh2[warp];
    }
}

// ---------------- host ----------------
extern "C" void kernel_launch(void* const* d_in, const int* in_sizes, int n_in,
                              void* d_out, int out_size){
    const float* x     = (const float*)d_in[0];
    const void*  ei    = d_in[1];
    const float* ea    = (const float*)d_in[2];
    const void*  batch = d_in[3];
    const float* W_in  = (const float*)d_in[4];
    const float* b_in  = (const float*)d_in[5];
    const float* Wq    = (const float*)d_in[6];
    const float* bq    = (const float*)d_in[7];
    const float* Wk    = (const float*)d_in[8];
    const float* bk    = (const float*)d_in[9];
    const float* Wv    = (const float*)d_in[10];
    const float* bv    = (const float*)d_in[11];
    const float* We    = (const float*)d_in[12];
    const float* be    = (const float*)d_in[13];
    const float* Wskip = (const float*)d_in[14];
    const float* bskip = (const float*)d_in[15];
    const float* Wbeta = (const float*)d_in[16];
    const float* Wg1   = (const float*)d_in[17];
    const float* bg1   = (const float*)d_in[18];
    const float* Wg2   = (const float*)d_in[19];
    const float* bg2   = (const float*)d_in[20];
    const float* Wh1   = (const float*)d_in[21];
    const float* bh1   = (const float*)d_in[22];
    const float* Wh2   = (const float*)d_in[23];
    const float* bh2   = (const float*)d_in[24];
    float* outp = (float*)d_out;

    void *ph0, *pxct, *pout, *pq, *pk, *pv, *ps;
    void *pwq, *pwk, *pwv, *pws, *pwg1;
    cudaGetSymbolAddress(&ph0, g_h0);
    cudaGetSymbolAddress(&pxct, g_xct);
    cudaGetSymbolAddress(&pout, g_out);
    cudaGetSymbolAddress(&pq, g_q);
    cudaGetSymbolAddress(&pk, g_k);
    cudaGetSymbolAddress(&pv, g_v);
    cudaGetSymbolAddress(&ps, g_skip);
    cudaGetSymbolAddress(&pwq, g_wq);
    cudaGetSymbolAddress(&pwk, g_wk);
    cudaGetSymbolAddress(&pwv, g_wv);
    cudaGetSymbolAddress(&pws, g_ws);
    cudaGetSymbolAddress(&pwg1, g_wg1);
    float* h0  = (float*)ph0;
    float* xct = (float*)pxct;
    float* tmp = (float*)pout;
    float* qp  = (float*)pq;
    float* kp  = (float*)pk;
    float* vp  = (float*)pv;
    float* sp  = (float*)ps;
    float* wq  = (float*)pwq;
    float* wk  = (float*)pwk;
    float* wv  = (float*)pwv;
    float* ws  = (float*)pws;
    float* wg1 = (float*)pwg1;

    static int smem_set = 0;
    if (!smem_set){
        cudaFuncSetAttribute(k_gemm_tf32, cudaFuncAttributeMaxDynamicSharedMemorySize, SMEM_GEMM);
        smem_set = 1;
    }

    k_detect<<<1, 256>>>(ei);
    k_convert<<<(2*Ee + 255)/256, 256>>>(ei, batch);
    k_cvtw<<<(4*2*HID*HID + JK*HID + 255)/256, 256>>>(Wq, Wk, Wv, Wskip, Wg1);
    k_count<<<(Ee + 255)/256, 256>>>();
    k_scan1<<<NBLK, 256>>>();
    k_scan2<<<1, 256>>>();
    k_scan3<<<NBLK, 256>>>();
    k_fill<<<(Ee + 255)/256, 256>>>(ea);

    k_input<<<Nn, HID>>>(x, W_in, b_in);

    for (int l = 0; l < 2; l++){
        const float* A = l ? xct : h0;
        int lda = l ? JK : HID;
        dim3 grid(5, (Nn + 127)/128);
        k_gemm_tf32<<<grid, 256, SMEM_GEMM>>>(A, lda, Nn, HID,
            wq + l*HID*HID, wk + l*HID*HID, wv + l*HID*HID, ws + l*HID*HID,
            bq + l*HID, bk + l*HID, bv + l*HID, bskip + l*HID,
            HID, 4*HID, qp, kp, vp, sp, 0);
        k_edge_alpha<<<Ee/32, 256>>>(We + l*4*HID, be + l*HID);
        k_node_soft<<<Nn/8, 256>>>();
        k_node_aggr<<<Nn/NPB, HID>>>(We + l*4*HID, be + l*HID);
        k_beta<<<Nn/8, 256>>>(Wbeta + l*3*HID, l);
    }

    {
        dim3 grid(2, (Nn + 127)/128);
        k_gemm_tf32<<<grid, 256, SMEM_GEMM>>>(xct, JK, Nn, JK,
            wg1, wg1, wg1, wg1, bg1, bg1, bg1, bg1,
            HID, HID, tmp, tmp, tmp, tmp, 1);
    }
    k_init_pool<<<40, 256>>>();
    k_gate<<<Nn/8, 256>>>(Wg2, bg2);
    k_ge<<<(Nn + 255)/256, 256>>>();
    k_att<<<(Nn + 255)/256, 256>>>();
    k_pool<<<(Nn + 127)/128, JK>>>();
    k_final<<<Gg, JK>>>(Wh1, bh1, Wh2, bh2, outp);
}

// round 15
// speedup vs baseline: 1.3858x; 1.3858x over previous
#include <cuda_runtime.h>
#include <math.h>

#define Nn 50000
#define Ee 500000
#define Gg 32
#define Hh 4
#define Dd 40
#define HID 160
#define JK 320
#define NBLK 196   // ceil(Nn/256)

// ---------------- scratch ----------------
__device__ float    g_h0[(size_t)Nn*HID];
__device__ float    g_q[(size_t)Nn*HID];
__device__ float    g_k[(size_t)Nn*HID];
__device__ float    g_v[(size_t)Nn*HID];
__device__ float    g_skip[(size_t)Nn*HID];
__device__ float    g_out[(size_t)Nn*HID];
__device__ float    g_xc[(size_t)Nn*JK];
__device__ float    g_xct[(size_t)Nn*JK];        // tf32-rounded copy for GEMM A
__device__ float    g_alpha[(size_t)Ee*Hh];      // slot-indexed
__device__ float    g_gate[Nn];
__device__ unsigned g_gmax[Gg];
__device__ float    g_gden[Gg];
__device__ float    g_pooled[Gg*JK];
__device__ int      g_ei32[(size_t)2*Ee];
__device__ int      g_batch32[Nn];
__device__ int      g_is64;
__device__ int      g_cnt[Nn];
__device__ int      g_rowptr[Nn+1];
__device__ int      g_fill[Nn];
__device__ int      g_srcs[Ee];                  // slot-ordered src node
__device__ int      g_dsts[Ee];                  // slot-ordered dst node
__device__ float4   g_eap[Ee];                   // slot-ordered edge attrs
__device__ int      g_bsum[NBLK];
__device__ int      g_boff[NBLK];
// tf32-rounded weights
__device__ float    g_wq[2*HID*HID];
__device__ float    g_wk[2*HID*HID];
__device__ float    g_wv[2*HID*HID];
__device__ float    g_ws[2*HID*HID];
__device__ float    g_wg1[JK*HID];

__device__ __forceinline__ unsigned fenc(float f){
    unsigned u = __float_as_uint(f);
    return (u & 0x80000000u) ? ~u : (u | 0x80000000u);
}
__device__ __forceinline__ float fdec(unsigned e){
    return (e & 0x80000000u) ? __uint_as_float(e ^ 0x80000000u) : __uint_as_float(~e);
}
__device__ __forceinline__ float rna_tf32(float f){
    unsigned u;
    asm("cvt.rna.tf32.f32 %0, %1;" : "=r"(u) : "f"(f));
    return __uint_as_float(u);
}

// ---------------- dtype detection + index normalization ----------------
__global__ void k_detect(const void* __restrict__ ei){
    const long long* p = (const long long*)ei;
    int bad = 0;
    for (int i = threadIdx.x; i < 4096; i += 256){
        long long v = p[i];
        if (v < 0 || v >= Nn) bad = 1;
    }
    bad = __syncthreads_or(bad);
    if (threadIdx.x == 0) g_is64 = bad ? 0 : 1;
}

__global__ void k_convert(const void* __restrict__ ei, const void* __restrict__ batch){
    int idx = blockIdx.x*blockDim.x + threadIdx.x;
    int is64 = g_is64;
    if (idx < 2*Ee){
        g_ei32[idx] = is64 ? (int)((const long long*)ei)[idx]
                           : ((const int*)ei)[idx];
    }
    if (idx < Nn){
        g_batch32[idx] = is64 ? (int)((const long long*)batch)[idx]
                              : ((const int*)batch)[idx];
        g_cnt[idx] = 0;
    }
}

// ---------------- weight rounding ----------------
__global__ void k_cvtw(const float* __restrict__ Wq, const float* __restrict__ Wk,
                       const float* __restrict__ Wv, const float* __restrict__ Ws,
                       const float* __restrict__ Wg1){
    int i = blockIdx.x*blockDim.x + threadIdx.x;
    const int n1 = 2*HID*HID;
    if (i < n1)            g_wq[i]        = rna_tf32(Wq[i]);
    else if (i < 2*n1)     g_wk[i-n1]     = rna_tf32(Wk[i-n1]);
    else if (i < 3*n1)     g_wv[i-2*n1]   = rna_tf32(Wv[i-2*n1]);
    else if (i < 4*n1)     g_ws[i-3*n1]   = rna_tf32(Ws[i-3*n1]);
    else if (i < 4*n1 + JK*HID) g_wg1[i-4*n1] = rna_tf32(Wg1[i-4*n1]);
}

// ---------------- CSR build ----------------
__global__ void k_count(){
    int e = blockIdx.x*blockDim.x + threadIdx.x;
    if (e < Ee) atomicAdd(&g_cnt[g_ei32[Ee + e]], 1);
}

__global__ __launch_bounds__(256) void k_scan1(){
    __shared__ int s[256];
    int t = threadIdx.x;
    int idx = blockIdx.x*256 + t;
    int v = (idx < Nn) ? g_cnt[idx] : 0;
    s[t] = v; __syncthreads();
#pragma unroll
    for (int off = 1; off < 256; off <<= 1){
        int x = (t >= off) ? s[t-off] : 0;
        __syncthreads();
        s[t] += x;
        __syncthreads();
    }
    if (idx < Nn) g_rowptr[idx] = s[t] - v;
    if (t == 255) g_bsum[blockIdx.x] = s[255];
}

__global__ __launch_bounds__(256) void k_scan2(){
    __shared__ int s[256];
    int t = threadIdx.x;
    int v = (t < NBLK) ? g_bsum[t] : 0;
    s[t] = v; __syncthreads();
#pragma unroll
    for (int off = 1; off < 256; off <<= 1){
        int x = (t >= off) ? s[t-off] : 0;
        __syncthreads();
        s[t] += x;
        __syncthreads();
    }
    if (t < NBLK) g_boff[t] = s[t] - v;
}

__global__ void k_scan3(){
    int idx = blockIdx.x*blockDim.x + threadIdx.x;
    if (idx < Nn){
        int r = g_rowptr[idx] + g_boff[idx >> 8];
        g_rowptr[idx] = r;
        g_fill[idx] = r;
    }
    if (idx == 0) g_rowptr[Nn] = Ee;
}

// fill slot-ordered edge arrays (src, dst, edge attrs)
__global__ void k_fill(const float* __restrict__ ea){
    int e = blockIdx.x*blockDim.x + threadIdx.x;
    if (e < Ee){
        int src = g_ei32[e];
        int dst = g_ei32[Ee + e];
        int slot = atomicAdd(&g_fill[dst], 1);
        g_srcs[slot] = src;
        g_dsts[slot] = dst;
        g_eap[slot]  = reinterpret_cast<const float4*>(ea)[e];
    }
}

// ---------------- input projection ----------------
__global__ __launch_bounds__(HID) void k_input(const float* __restrict__ x,
                                               const float* __restrict__ W,
                                               const float* __restrict__ b){
    int n = blockIdx.x, c = threadIdx.x;
    __shared__ float xr[5];
    if (c < 5) xr[c] = x[n*5 + c];
    __syncthreads();
    float acc = b[c];
#pragma unroll
    for (int j = 0; j < 5; j++) acc = fmaf(xr[j], W[j*HID + c], acc);
    g_h0[(size_t)n*HID + c] = rna_tf32(acc);
}

// ---------------- TF32 tensor-core GEMM, cp.async double-buffered -------------
#define SA_STR 36
#define SB_STR 136
#define SMEM_GEMM ((2*128*SA_STR + 2*32*SB_STR)*4)

#define STAGE(buf_, k0_) do{ \
    _Pragma("unroll") \
    for (int r_ = 0; r_ < 4; r_++){ \
        int s_ = tid + 256*r_; \
        int row_ = s_ >> 3, c4_ = (s_ & 7) << 2; \
        const float* src_ = A + (size_t)(bm+row_)*lda + (k0_) + c4_; \
        int sz_ = (bm + row_ < M) ? 16 : 0; \
        if (!sz_) src_ = A; \
        unsigned da_ = sbase + (unsigned)(((buf_)*128*SA_STR + row_*SA_STR + c4_)*4); \
        asm volatile("cp.async.ca.shared.global [%0], [%1], 16, %2;" \
                     :: "r"(da_), "l"(src_), "r"(sz_)); \
    } \
    _Pragma("unroll") \
    for (int r_ = 0; r_ < 4; r_++){ \
        int kr_ = (tid >> 5) + 8*r_; \
        const float* src_ = Bm ? (Bm + (size_t)((k0_)+kr_)*matcols + bc2) : A; \
        int sz_ = Bm ? 16 : 0; \
        unsigned db_ = sbbase + (unsigned)(((buf_)*32*SB_STR + kr_*SB_STR + nc)*4); \
        asm volatile("cp.async.ca.shared.global [%0], [%1], 16, %2;" \
                     :: "r"(db_), "l"(src_), "r"(sz_)); \
    } \
    asm volatile("cp.async.commit_group;"); \
}while(0)

__global__ __launch_bounds__(256,2) void k_gemm_tf32(
    const float* __restrict__ A, int lda, int M, int K,
    const float* __restrict__ B0, const float* __restrict__ B1,
    const float* __restrict__ B2, const float* __restrict__ B3,
    const float* __restrict__ bias0, const float* __restrict__ bias1,
    const float* __restrict__ bias2, const float* __restrict__ bias3,
    int matcols, int Ntot,
    float* __restrict__ C0, float* __restrict__ C1,
    float* __restrict__ C2, float* __restrict__ C3, int relu)
{
    extern __shared__ float smem[];
    float* sA = smem;
    float* sB = smem + 2*128*SA_STR;
    int tid = threadIdx.x;
    int bm = blockIdx.y*128, bn = blockIdx.x*128;
    int warp = tid >> 5, lane = tid & 31;
    int wm = (warp & 1)*64, wn = (warp >> 1)*32;
    int g = lane >> 2, l4 = lane & 3;

    unsigned sbase  = (unsigned)__cvta_generic_to_shared(sA);
    unsigned sbbase = (unsigned)__cvta_generic_to_shared(sB);

    int nc = (tid & 31) << 2;
    int col_st = bn + nc;
    const float* Bm = nullptr; int bc2 = 0;
    if (col_st < Ntot){
        int m = col_st / matcols;
        bc2 = col_st - m*matcols;
        Bm = (m==0)?B0:(m==1)?B1:(m==2)?B2:B3;
    }

    float acc[4][4][4];
#pragma unroll
    for (int i = 0; i < 4; i++)
#pragma unroll
        for (int j = 0; j < 4; j++)
#pragma unroll
            for (int r = 0; r < 4; r++) acc[i][j][r] = 0.f;

    STAGE(0, 0);
    int nt = K >> 5;
    for (int t = 0; t < nt; t++){
        int buf = t & 1;
        if (t+1 < nt){
            STAGE(buf^1, (t+1)*32);
            asm volatile("cp.async.wait_group 1;");
        } else {
            asm volatile("cp.async.wait_group 0;");
        }
        __syncthreads();

        const unsigned* uA = reinterpret_cast<const unsigned*>(sA + buf*128*SA_STR);
        const unsigned* uB = reinterpret_cast<const unsigned*>(sB + buf*32*SB_STR);
#pragma unroll
        for (int k8 = 0; k8 < 4; k8++){
            unsigned a[4][4], b[4][2];
            int c0 = k8*8 + l4;
#pragma unroll
            for (int i = 0; i < 4; i++){
                int r0 = wm + i*16 + g;
                a[i][0] = uA[r0*SA_STR + c0];
                a[i][1] = uA[(r0+8)*SA_STR + c0];
                a[i][2] = uA[r0*SA_STR + c0 + 4];
                a[i][3] = uA[(r0+8)*SA_STR + c0 + 4];
            }
#pragma unroll
            for (int j = 0; j < 4; j++){
                int nn = wn + j*8 + g;
                b[j][0] = uB[(k8*8 + l4)*SB_STR + nn];
                b[j][1] = uB[(k8*8 + l4 + 4)*SB_STR + nn];
            }
#pragma unroll
            for (int i = 0; i < 4; i++)
#pragma unroll
                for (int j = 0; j < 4; j++){
                    asm volatile(
                        "mma.sync.aligned.m16n8k8.row.col.f32.tf32.tf32.f32 "
                        "{%0,%1,%2,%3}, {%4,%5,%6,%7}, {%8,%9}, {%0,%1,%2,%3};\n"
                        : "+f"(acc[i][j][0]), "+f"(acc[i][j][1]),
                          "+f"(acc[i][j][2]), "+f"(acc[i][j][3])
                        : "r"(a[i][0]), "r"(a[i][1]), "r"(a[i][2]), "r"(a[i][3]),
                          "r"(b[j][0]), "r"(b[j][1]));
                }
        }
        __syncthreads();
    }

#pragma unroll
    for (int j = 0; j < 4; j++){
        int col = bn + wn + j*8 + 2*l4;
        if (col >= Ntot) continue;
        int m  = col / matcols;
        int c2 = col - m*matcols;
        const float* bp = (m==0)?bias0:(m==1)?bias1:(m==2)?bias2:bias3;
        float*       Cm = (m==0)?C0:(m==1)?C1:(m==2)?C2:C3;
        float bx = bp[c2], by = bp[c2+1];
#pragma unroll
        for (int i = 0; i < 4; i++){
            int row0 = bm + wm + i*16 + g;
            float vx, vy;
            if (row0 < M){
                vx = acc[i][j][0] + bx; vy = acc[i][j][1] + by;
                if (relu){ vx = fmaxf(vx, 0.f); vy = fmaxf(vy, 0.f); }
                *reinterpret_cast<float2*>(Cm + (size_t)row0*matcols + c2) = make_float2(vx, vy);
            }
            int row1 = row0 + 8;
            if (row1 < M){
                vx = acc[i][j][2] + bx; vy = acc[i][j][3] + by;
                if (relu){ vx = fmaxf(vx, 0.f); vy = fmaxf(vy, 0.f); }
                *reinterpret_cast<float2*>(Cm + (size_t)row1*matcols + c2) = make_float2(vx, vy);
            }
        }
    }
}

// ---------------- edge: alpha logits over CSR slots (4 slots per warp) --------
__global__ __launch_bounds__(256) void k_edge_alpha(
    const float* __restrict__ We, const float* __restrict__ be)
{
    __shared__ float sWe[4*HID];
    __shared__ float sbe[HID];
    int t = threadIdx.x;
    for (int i = t; i < 4*HID; i += 256) sWe[i] = We[i];
    if (t < HID) sbe[t] = be[t];
    __syncthreads();
    int warp = t >> 5, lane = t & 31;
    int hh = lane >> 3, o = lane & 7;
    int cb = hh*Dd + o;
#pragma unroll
    for (int i4 = 0; i4 < 4; i4++){
        int s = blockIdx.x*32 + warp + 8*i4;
        int src = g_srcs[s];
        int dst = g_dsts[s];
        float4 ej = g_eap[s];
        const float* qr = g_q + (size_t)dst*HID;
        const float* kr = g_k + (size_t)src*HID;
        float part = 0.f;
#pragma unroll
        for (int i = 0; i < 5; i++){
            int c = cb + 8*i;
            float ev = sbe[c] + ej.x*sWe[c] + ej.y*sWe[HID+c] + ej.z*sWe[2*HID+c] + ej.w*sWe[3*HID+c];
            part = fmaf(qr[c], kr[c] + ev, part);
        }
        part += __shfl_down_sync(0xffffffffu, part, 4, 8);
        part += __shfl_down_sync(0xffffffffu, part, 2, 8);
        part += __shfl_down_sync(0xffffffffu, part, 1, 8);
        if (o == 0)
            g_alpha[(size_t)s*4 + hh] = part * 0.15811388300841897f;
    }
}

// ---------------- per-node softmax (contiguous alpha) ----------------
__global__ __launch_bounds__(256) void k_node_soft(){
    int t = threadIdx.x, warp = t >> 5, lane = t & 31;
    int n = blockIdx.x*8 + warp;
    int beg = g_rowptr[n], end = g_rowptr[n+1];
    int deg = end - beg;
    if (deg == 0) return;
    float4* al4 = reinterpret_cast<float4*>(g_alpha);

    float m0=-3.4e38f, m1=-3.4e38f, m2=-3.4e38f, m3=-3.4e38f;
    for (int i = lane; i < deg; i += 32){
        float4 a = al4[beg + i];
        m0 = fmaxf(m0, a.x); m1 = fmaxf(m1, a.y);
        m2 = fmaxf(m2, a.z); m3 = fmaxf(m3, a.w);
    }
#pragma unroll
    for (int off = 16; off; off >>= 1){
        m0 = fmaxf(m0, __shfl_xor_sync(0xffffffffu, m0, off));
        m1 = fmaxf(m1, __shfl_xor_sync(0xffffffffu, m1, off));
        m2 = fmaxf(m2, __shfl_xor_sync(0xffffffffu, m2, off));
        m3 = fmaxf(m3, __shfl_xor_sync(0xffffffffu, m3, off));
    }
    float s0=0.f, s1=0.f, s2=0.f, s3=0.f;
    for (int i = lane; i < deg; i += 32){
        float4 a = al4[beg + i];
        a.x = expf(a.x - m0); a.y = expf(a.y - m1);
        a.z = expf(a.z - m2); a.w = expf(a.w - m3);
        s0 += a.x; s1 += a.y; s2 += a.z; s3 += a.w;
        al4[beg + i] = a;
    }
#pragma unroll
    for (int off = 16; off; off >>= 1){
        s0 += __shfl_xor_sync(0xffffffffu, s0, off);
        s1 += __shfl_xor_sync(0xffffffffu, s1, off);
        s2 += __shfl_xor_sync(0xffffffffu, s2, off);
        s3 += __shfl_xor_sync(0xffffffffu, s3, off);
    }
    float r0 = 1.f/s0, r1 = 1.f/s1, r2 = 1.f/s2, r3 = 1.f/s3;
    for (int i = lane; i < deg; i += 32){
        float4 a = al4[beg + i];
        a.x *= r0; a.y *= r1; a.z *= r2; a.w *= r3;
        al4[beg + i] = a;
    }
}

// ---------------- per-node aggregation (8 nodes per block, contiguous staging) -
#define ECH 64
#define NPB 8
__global__ __launch_bounds__(HID) void k_node_aggr(
    const float* __restrict__ We, const float* __restrict__ be)
{
    __shared__ float sWe[4*HID];
    __shared__ float sbe[HID];
    __shared__ float4 s_ea[ECH];
    __shared__ float4 s_a[ECH];
    __shared__ int    s_src[ECH];
    int c = threadIdx.x;
    for (int i = c; i < 4*HID; i += HID) sWe[i] = We[i];
    sbe[c] = be[c];
    int h = c / Dd;
    const float4* al4 = reinterpret_cast<const float4*>(g_alpha);

    for (int nn = 0; nn < NPB; nn++){
        int n = blockIdx.x*NPB + nn;
        int beg = g_rowptr[n], end = g_rowptr[n+1];
        float acc = 0.f;
        for (int base = beg; base < end; base += ECH){
            int m = min(ECH, end - base);
            __syncthreads();
            if (c < m){
                s_src[c] = g_srcs[base + c];
                s_ea[c]  = g_eap[base + c];
                s_a[c]   = al4[base + c];
            }
            __syncthreads();
            for (int j = 0; j < m; j++){
                float4 ej = s_ea[j];
                float w = reinterpret_cast<const float*>(&s_a[j])[h];
                float ev = sbe[c] + ej.x*sWe[c] + ej.y*sWe[HID+c]
                         + ej.z*sWe[2*HID+c] + ej.w*sWe[3*HID+c];
                acc = fmaf(g_v[(size_t)s_src[j]*HID + c] + ev, w, acc);
            }
        }
        g_out[(size_t)n*HID + c] = acc;
    }
}

// ---------------- beta gate + combine (writes f32 xc + rounded xct) ----------
__global__ __launch_bounds__(256) void k_beta(const float* __restrict__ Wb, int l){
    int t = threadIdx.x, warp = t >> 5, lane = t & 31;
    int n = blockIdx.x*8 + warp;
    const float* o = g_out  + (size_t)n*HID;
    const float* r = g_skip + (size_t)n*HID;
    float oc[5], rc[5];
    float p = 0.f;
#pragma unroll
    for (int i = 0; i < 5; i++){
        int c = lane + 32*i;
        oc[i] = o[c]; rc[i] = r[c];
        p += oc[i]*Wb[c] + rc[i]*Wb[HID+c] + (oc[i]-rc[i])*Wb[2*HID+c];
    }
#pragma unroll
    for (int off = 16; off; off >>= 1) p += __shfl_xor_sync(0xffffffffu, p, off);
    float beta = 1.f/(1.f + expf(-p));
    float* hx  = g_xc  + (size_t)n*JK + (size_t)l*HID;
    float* hxt = g_xct + (size_t)n*JK + (size_t)l*HID;
#pragma unroll
    for (int i = 0; i < 5; i++){
        int c = lane + 32*i;
        float v = beta*rc[i] + (1.f - beta)*oc[i];
        hx[c]  = v;
        hxt[c] = rna_tf32(v);
    }
}

// ---------------- pooling ----------------
__global__ void k_init_pool(){
    int idx = blockIdx.x*blockDim.x + threadIdx.x;
    if (idx < Gg){ g_gmax[idx] = 0u; g_gden[idx] = 0.f; }
    if (idx < Gg*JK) g_pooled[idx] = 0.f;
}

__global__ __launch_bounds__(256) void k_gate(const float* __restrict__ Wg2,
                                              const float* __restrict__ bg2){
    int t = threadIdx.x, warp = t >> 5, lane = t & 31;
    int n = blockIdx.x*8 + warp;
    const float* tp = g_out + (size_t)n*HID;
    float p = 0.f;
#pragma unroll
    for (int i = 0; i < 5; i++){
        int c = lane + 32*i;
        p = fmaf(tp[c], Wg2[c], p);
    }
#pragma unroll
    for (int off = 16; off; off >>= 1) p += __shfl_xor_sync(0xffffffffu, p, off);
    if (lane == 0){
        float gate = p + bg2[0];
        g_gate[n] = gate;
        atomicMax(&g_gmax[g_batch32[n]], fenc(gate));
    }
}

__global__ void k_ge(){
    __shared__ float s[Gg];
    int t = threadIdx.x;
    if (t < Gg) s[t] = 0.f;
    __syncthreads();
    int n = blockIdx.x*blockDim.x + t;
    if (n < Nn){
        int b = g_batch32[n];
        float ge = expf(g_gate[n] - fdec(g_gmax[b]));
        g_gate[n] = ge;
        atomicAdd(&s[b], ge);
    }
    __syncthreads();
    if (t < Gg) atomicAdd(&g_gden[t], s[t]);
}

__global__ void k_att(){
    int n = blockIdx.x*blockDim.x + threadIdx.x;
    if (n < Nn) g_gate[n] /= g_gden[g_batch32[n]];
}

__global__ __launch_bounds__(JK) void k_pool(){
    int c = threadIdx.x;
    int n0 = blockIdx.x*128;
    if (n0 >= Nn) return;
    int nend = min(n0 + 128, Nn);
    int curg = g_batch32[n0];
    float acc = 0.f;
    for (int n = n0; n < nend; n++){
        int g = g_batch32[n];
        if (g != curg){
            atomicAdd(&g_pooled[curg*JK + c], acc);
            acc = 0.f; curg = g;
        }
        acc = fmaf(g_gate[n], g_xc[(size_t)n*JK + c], acc);
    }
    atomicAdd(&g_pooled[curg*JK + c], acc);
}

__global__ __launch_bounds__(JK) void k_final(const float* __restrict__ Wh1,
                                              const float* __restrict__ bh1,
                                              const float* __restrict__ Wh2,
                                              const float* __restrict__ bh2,
                                              float* __restrict__ outp){
    __shared__ float p[JK];
    __shared__ float t1[JK];
    int g = blockIdx.x, c = threadIdx.x;
    p[c] = g_pooled[g*JK + c];
    __syncthreads();
    float acc = bh1[c];
    for (int k = 0; k < JK; k++) acc = fmaf(p[k], Wh1[k*JK + c], acc);
    t1[c] = fmaxf(acc, 0.f);
    __syncthreads();
    int warp = c >> 5, lane = c & 31;
    if (warp < 6){
        float s = 0.f;
        for (int k = lane; k < JK; k += 32) s = fmaf(t1[k], Wh2[k*6 + warp], s);
#pragma unroll
        for (int off = 16; off; off >>= 1) s += __shfl_xor_sync(0xffffffffu, s, off);
        if (lane == 0) outp[g*6 + warp] = s + bh2[warp];
    }
}

// ---------------- host ----------------
extern "C" void kernel_launch(void* const* d_in, const int* in_sizes, int n_in,
                              void* d_out, int out_size){
    const float* x     = (const float*)d_in[0];
    const void*  ei    = d_in[1];
    const float* ea    = (const float*)d_in[2];
    const void*  batch = d_in[3];
    const float* W_in  = (const float*)d_in[4];
    const float* b_in  = (const float*)d_in[5];
    const float* Wq    = (const float*)d_in[6];
    const float* bq    = (const float*)d_in[7];
    const float* Wk    = (const float*)d_in[8];
    const float* bk    = (const float*)d_in[9];
    const float* Wv    = (const float*)d_in[10];
    const float* bv    = (const float*)d_in[11];
    const float* We    = (const float*)d_in[12];
    const float* be    = (const float*)d_in[13];
    const float* Wskip = (const float*)d_in[14];
    const float* bskip = (const float*)d_in[15];
    const float* Wbeta = (const float*)d_in[16];
    const float* Wg1   = (const float*)d_in[17];
    const float* bg1   = (const float*)d_in[18];
    const float* Wg2   = (const float*)d_in[19];
    const float* bg2   = (const float*)d_in[20];
    const float* Wh1   = (const float*)d_in[21];
    const float* bh1   = (const float*)d_in[22];
    const float* Wh2   = (const float*)d_in[23];
    const float* bh2   = (const float*)d_in[24];
    float* outp = (float*)d_out;

    void *ph0, *pxct, *pout, *pq, *pk, *pv, *ps;
    void *pwq, *pwk, *pwv, *pws, *pwg1;
    cudaGetSymbolAddress(&ph0, g_h0);
    cudaGetSymbolAddress(&pxct, g_xct);
    cudaGetSymbolAddress(&pout, g_out);
    cudaGetSymbolAddress(&pq, g_q);
    cudaGetSymbolAddress(&pk, g_k);
    cudaGetSymbolAddress(&pv, g_v);
    cudaGetSymbolAddress(&ps, g_skip);
    cudaGetSymbolAddress(&pwq, g_wq);
    cudaGetSymbolAddress(&pwk, g_wk);
    cudaGetSymbolAddress(&pwv, g_wv);
    cudaGetSymbolAddress(&pws, g_ws);
    cudaGetSymbolAddress(&pwg1, g_wg1);
    float* h0  = (float*)ph0;
    float* xct = (float*)pxct;
    float* tmp = (float*)pout;
    float* qp  = (float*)pq;
    float* kp  = (float*)pk;
    float* vp  = (float*)pv;
    float* sp  = (float*)ps;
    float* wq  = (float*)pwq;
    float* wk  = (float*)pwk;
    float* wv  = (float*)pwv;
    float* ws  = (float*)pws;
    float* wg1 = (float*)pwg1;

    static int smem_set = 0;
    if (!smem_set){
        cudaFuncSetAttribute(k_gemm_tf32, cudaFuncAttributeMaxDynamicSharedMemorySize, SMEM_GEMM);
        smem_set = 1;
    }

    k_detect<<<1, 256>>>(ei);
    k_convert<<<(2*Ee + 255)/256, 256>>>(ei, batch);
    k_cvtw<<<(4*2*HID*HID + JK*HID + 255)/256, 256>>>(Wq, Wk, Wv, Wskip, Wg1);
    k_count<<<(Ee + 255)/256, 256>>>();
    k_scan1<<<NBLK, 256>>>();
    k_scan2<<<1, 256>>>();
    k_scan3<<<NBLK, 256>>>();
    k_fill<<<(Ee + 255)/256, 256>>>(ea);

    k_input<<<Nn, HID>>>(x, W_in, b_in);

    for (int l = 0; l < 2; l++){
        const float* A = l ? xct : h0;
        int lda = l ? JK : HID;
        dim3 grid(5, (Nn + 127)/128);
        k_gemm_tf32<<<grid, 256, SMEM_GEMM>>>(A, lda, Nn, HID,
            wq + l*HID*HID, wk + l*HID*HID, wv + l*HID*HID, ws + l*HID*HID,
            bq + l*HID, bk + l*HID, bv + l*HID, bskip + l*HID,
            HID, 4*HID, qp, kp, vp, sp, 0);
        k_edge_alpha<<<Ee/32, 256>>>(We + l*4*HID, be + l*HID);
        k_node_soft<<<Nn/8, 256>>>();
        k_node_aggr<<<Nn/NPB, HID>>>(We + l*4*HID, be + l*HID);
        k_beta<<<Nn/8, 256>>>(Wbeta + l*3*HID, l);
    }

    {
        dim3 grid(2, (Nn + 127)/128);
        k_gemm_tf32<<<grid, 256, SMEM_GEMM>>>(xct, JK, Nn, JK,
            wg1, wg1, wg1, wg1, bg1, bg1, bg1, bg1,
            HID, HID, tmp, tmp, tmp, tmp, 1);
    }
    k_init_pool<<<40, 256>>>();
    k_gate<<<Nn/8, 256>>>(Wg2, bg2);
    k_ge<<<(Nn + 255)/256, 256>>>();
    k_att<<<(Nn + 255)/256, 256>>>();
    k_pool<<<(Nn + 127)/128, JK>>>();
    k_final<<<Gg, JK>>>(Wh1, bh1, Wh2, bh2, outp);
}

// round 16
// speedup vs baseline: 1.3891x; 1.0023x over previous
#include <cuda_runtime.h>
#include <math.h>

#define Nn 50000
#define Ee 500000
#define Gg 32
#define Hh 4
#define Dd 40
#define HID 160
#define JK 320
#define NBLK 196   // ceil(Nn/256)

// ---------------- scratch ----------------
__device__ float    g_h0[(size_t)Nn*HID];
__device__ float    g_q[(size_t)Nn*HID];
__device__ float    g_k[(size_t)Nn*HID];
__device__ float    g_v[(size_t)Nn*HID];
__device__ float    g_skip[(size_t)Nn*HID];
__device__ float    g_out[(size_t)Nn*HID];
__device__ float    g_xc[(size_t)Nn*JK];
__device__ float    g_xct[(size_t)Nn*JK];        // tf32-rounded copy for GEMM A
__device__ float    g_alpha[(size_t)Ee*Hh];      // slot-indexed
__device__ float    g_gate[Nn];
__device__ unsigned g_gmax[Gg];
__device__ float    g_gden[Gg];
__device__ float    g_pooled[Gg*JK];
__device__ int      g_ei32[(size_t)2*Ee];
__device__ int      g_batch32[Nn];
__device__ int      g_is64;
__device__ int      g_cnt[Nn];
__device__ int      g_rowptr[Nn+1];
__device__ int      g_fill[Nn];
__device__ int      g_srcs[Ee];                  // slot-ordered src node
__device__ int      g_dsts[Ee];                  // slot-ordered dst node
__device__ float4   g_eap[Ee];                   // slot-ordered edge attrs
__device__ int      g_bsum[NBLK];
__device__ int      g_boff[NBLK];
// tf32-rounded weights
__device__ float    g_wq[2*HID*HID];
__device__ float    g_wk[2*HID*HID];
__device__ float    g_wv[2*HID*HID];
__device__ float    g_ws[2*HID*HID];
__device__ float    g_wg1[JK*HID];

__device__ __forceinline__ unsigned fenc(float f){
    unsigned u = __float_as_uint(f);
    return (u & 0x80000000u) ? ~u : (u | 0x80000000u);
}
__device__ __forceinline__ float fdec(unsigned e){
    return (e & 0x80000000u) ? __uint_as_float(e ^ 0x80000000u) : __uint_as_float(~e);
}
__device__ __forceinline__ float rna_tf32(float f){
    unsigned u;
    asm("cvt.rna.tf32.f32 %0, %1;" : "=r"(u) : "f"(f));
    return __uint_as_float(u);
}

// ---------------- dtype detection ----------------
__global__ void k_detect(const void* __restrict__ ei){
    const long long* p = (const long long*)ei;
    int bad = 0;
    for (int i = threadIdx.x; i < 4096; i += 256){
        long long v = p[i];
        if (v < 0 || v >= Nn) bad = 1;
    }
    bad = __syncthreads_or(bad);
    if (threadIdx.x == 0) g_is64 = bad ? 0 : 1;
}

// ---------------- zero degree counters (before convert counts) ----------------
__global__ void k_zero_cnt(){
    int idx = blockIdx.x*blockDim.x + threadIdx.x;
    if (idx < Nn) g_cnt[idx] = 0;
}

// ---------------- index normalization + degree count (fused) ----------------
__global__ void k_convert(const void* __restrict__ ei, const void* __restrict__ batch){
    int idx = blockIdx.x*blockDim.x + threadIdx.x;
    int is64 = g_is64;
    if (idx < 2*Ee){
        int v = is64 ? (int)((const long long*)ei)[idx]
                     : ((const int*)ei)[idx];
        g_ei32[idx] = v;
        if (idx >= Ee) atomicAdd(&g_cnt[v], 1);
    }
    if (idx < Nn){
        g_batch32[idx] = is64 ? (int)((const long long*)batch)[idx]
                              : ((const int*)batch)[idx];
    }
}

// ---------------- weight rounding ----------------
__global__ void k_cvtw(const float* __restrict__ Wq, const float* __restrict__ Wk,
                       const float* __restrict__ Wv, const float* __restrict__ Ws,
                       const float* __restrict__ Wg1){
    int i = blockIdx.x*blockDim.x + threadIdx.x;
    const int n1 = 2*HID*HID;
    if (i < n1)            g_wq[i]        = rna_tf32(Wq[i]);
    else if (i < 2*n1)     g_wk[i-n1]     = rna_tf32(Wk[i-n1]);
    else if (i < 3*n1)     g_wv[i-2*n1]   = rna_tf32(Wv[i-2*n1]);
    else if (i < 4*n1)     g_ws[i-3*n1]   = rna_tf32(Ws[i-3*n1]);
    else if (i < 4*n1 + JK*HID) g_wg1[i-4*n1] = rna_tf32(Wg1[i-4*n1]);
}

// ---------------- CSR build ----------------
__global__ __launch_bounds__(256) void k_scan1(){
    __shared__ int s[256];
    int t = threadIdx.x;
    int idx = blockIdx.x*256 + t;
    int v = (idx < Nn) ? g_cnt[idx] : 0;
    s[t] = v; __syncthreads();
#pragma unroll
    for (int off = 1; off < 256; off <<= 1){
        int x = (t >= off) ? s[t-off] : 0;
        __syncthreads();
        s[t] += x;
        __syncthreads();
    }
    if (idx < Nn) g_rowptr[idx] = s[t] - v;
    if (t == 255) g_bsum[blockIdx.x] = s[255];
}

__global__ __launch_bounds__(256) void k_scan2(){
    __shared__ int s[256];
    int t = threadIdx.x;
    int v = (t < NBLK) ? g_bsum[t] : 0;
    s[t] = v; __syncthreads();
#pragma unroll
    for (int off = 1; off < 256; off <<= 1){
        int x = (t >= off) ? s[t-off] : 0;
        __syncthreads();
        s[t] += x;
        __syncthreads();
    }
    if (t < NBLK) g_boff[t] = s[t] - v;
}

__global__ void k_scan3(){
    int idx = blockIdx.x*blockDim.x + threadIdx.x;
    if (idx < Nn){
        int r = g_rowptr[idx] + g_boff[idx >> 8];
        g_rowptr[idx] = r;
        g_fill[idx] = r;
    }
    if (idx == 0) g_rowptr[Nn] = Ee;
}

// fill slot-ordered edge arrays (src, dst, edge attrs)
__global__ void k_fill(const float* __restrict__ ea){
    int e = blockIdx.x*blockDim.x + threadIdx.x;
    if (e < Ee){
        int src = g_ei32[e];
        int dst = g_ei32[Ee + e];
        int slot = atomicAdd(&g_fill[dst], 1);
        g_srcs[slot] = src;
        g_dsts[slot] = dst;
        g_eap[slot]  = reinterpret_cast<const float4*>(ea)[e];
    }
}

// ---------------- input projection ----------------
__global__ __launch_bounds__(HID) void k_input(const float* __restrict__ x,
                                               const float* __restrict__ W,
                                               const float* __restrict__ b){
    int n = blockIdx.x, c = threadIdx.x;
    __shared__ float xr[5];
    if (c < 5) xr[c] = x[n*5 + c];
    __syncthreads();
    float acc = b[c];
#pragma unroll
    for (int j = 0; j < 5; j++) acc = fmaf(xr[j], W[j*HID + c], acc);
    g_h0[(size_t)n*HID + c] = rna_tf32(acc);
}

// ---------------- TF32 tensor-core GEMM, cp.async double-buffered -------------
#define SA_STR 36
#define SB_STR 136
#define SMEM_GEMM ((2*128*SA_STR + 2*32*SB_STR)*4)

#define STAGE(buf_, k0_) do{ \
    _Pragma("unroll") \
    for (int r_ = 0; r_ < 4; r_++){ \
        int s_ = tid + 256*r_; \
        int row_ = s_ >> 3, c4_ = (s_ & 7) << 2; \
        const float* src_ = A + (size_t)(bm+row_)*lda + (k0_) + c4_; \
        int sz_ = (bm + row_ < M) ? 16 : 0; \
        if (!sz_) src_ = A; \
        unsigned da_ = sbase + (unsigned)(((buf_)*128*SA_STR + row_*SA_STR + c4_)*4); \
        asm volatile("cp.async.ca.shared.global [%0], [%1], 16, %2;" \
                     :: "r"(da_), "l"(src_), "r"(sz_)); \
    } \
    _Pragma("unroll") \
    for (int r_ = 0; r_ < 4; r_++){ \
        int kr_ = (tid >> 5) + 8*r_; \
        const float* src_ = Bm ? (Bm + (size_t)((k0_)+kr_)*matcols + bc2) : A; \
        int sz_ = Bm ? 16 : 0; \
        unsigned db_ = sbbase + (unsigned)(((buf_)*32*SB_STR + kr_*SB_STR + nc)*4); \
        asm volatile("cp.async.ca.shared.global [%0], [%1], 16, %2;" \
                     :: "r"(db_), "l"(src_), "r"(sz_)); \
    } \
    asm volatile("cp.async.commit_group;"); \
}while(0)

__global__ __launch_bounds__(256,2) void k_gemm_tf32(
    const float* __restrict__ A, int lda, int M, int K,
    const float* __restrict__ B0, const float* __restrict__ B1,
    const float* __restrict__ B2, const float* __restrict__ B3,
    const float* __restrict__ bias0, const float* __restrict__ bias1,
    const float* __restrict__ bias2, const float* __restrict__ bias3,
    int matcols, int Ntot,
    float* __restrict__ C0, float* __restrict__ C1,
    float* __restrict__ C2, float* __restrict__ C3, int relu)
{
    extern __shared__ float smem[];
    float* sA = smem;
    float* sB = smem + 2*128*SA_STR;
    int tid = threadIdx.x;
    int bm = blockIdx.y*128, bn = blockIdx.x*128;
    int warp = tid >> 5, lane = tid & 31;
    int wm = (warp & 1)*64, wn = (warp >> 1)*32;
    int g = lane >> 2, l4 = lane & 3;

    unsigned sbase  = (unsigned)__cvta_generic_to_shared(sA);
    unsigned sbbase = (unsigned)__cvta_generic_to_shared(sB);

    int nc = (tid & 31) << 2;
    int col_st = bn + nc;
    const float* Bm = nullptr; int bc2 = 0;
    if (col_st < Ntot){
        int m = col_st / matcols;
        bc2 = col_st - m*matcols;
        Bm = (m==0)?B0:(m==1)?B1:(m==2)?B2:B3;
    }

    float acc[4][4][4];
#pragma unroll
    for (int i = 0; i < 4; i++)
#pragma unroll
        for (int j = 0; j < 4; j++)
#pragma unroll
            for (int r = 0; r < 4; r++) acc[i][j][r] = 0.f;

    STAGE(0, 0);
    int nt = K >> 5;
    for (int t = 0; t < nt; t++){
        int buf = t & 1;
        if (t+1 < nt){
            STAGE(buf^1, (t+1)*32);
            asm volatile("cp.async.wait_group 1;");
        } else {
            asm volatile("cp.async.wait_group 0;");
        }
        __syncthreads();

        const unsigned* uA = reinterpret_cast<const unsigned*>(sA + buf*128*SA_STR);
        const unsigned* uB = reinterpret_cast<const unsigned*>(sB + buf*32*SB_STR);
#pragma unroll
        for (int k8 = 0; k8 < 4; k8++){
            unsigned a[4][4], b[4][2];
            int c0 = k8*8 + l4;
#pragma unroll
            for (int i = 0; i < 4; i++){
                int r0 = wm + i*16 + g;
                a[i][0] = uA[r0*SA_STR + c0];
                a[i][1] = uA[(r0+8)*SA_STR + c0];
                a[i][2] = uA[r0*SA_STR + c0 + 4];
                a[i][3] = uA[(r0+8)*SA_STR + c0 + 4];
            }
#pragma unroll
            for (int j = 0; j < 4; j++){
                int nn = wn + j*8 + g;
                b[j][0] = uB[(k8*8 + l4)*SB_STR + nn];
                b[j][1] = uB[(k8*8 + l4 + 4)*SB_STR + nn];
            }
#pragma unroll
            for (int i = 0; i < 4; i++)
#pragma unroll
                for (int j = 0; j < 4; j++){
                    asm volatile(
                        "mma.sync.aligned.m16n8k8.row.col.f32.tf32.tf32.f32 "
                        "{%0,%1,%2,%3}, {%4,%5,%6,%7}, {%8,%9}, {%0,%1,%2,%3};\n"
                        : "+f"(acc[i][j][0]), "+f"(acc[i][j][1]),
                          "+f"(acc[i][j][2]), "+f"(acc[i][j][3])
                        : "r"(a[i][0]), "r"(a[i][1]), "r"(a[i][2]), "r"(a[i][3]),
                          "r"(b[j][0]), "r"(b[j][1]));
                }
        }
        __syncthreads();
    }

#pragma unroll
    for (int j = 0; j < 4; j++){
        int col = bn + wn + j*8 + 2*l4;
        if (col >= Ntot) continue;
        int m  = col / matcols;
        int c2 = col - m*matcols;
        const float* bp = (m==0)?bias0:(m==1)?bias1:(m==2)?bias2:bias3;
        float*       Cm = (m==0)?C0:(m==1)?C1:(m==2)?C2:C3;
        float bx = bp[c2], by = bp[c2+1];
#pragma unroll
        for (int i = 0; i < 4; i++){
            int row0 = bm + wm + i*16 + g;
            float vx, vy;
            if (row0 < M){
                vx = acc[i][j][0] + bx; vy = acc[i][j][1] + by;
                if (relu){ vx = fmaxf(vx, 0.f); vy = fmaxf(vy, 0.f); }
                *reinterpret_cast<float2*>(Cm + (size_t)row0*matcols + c2) = make_float2(vx, vy);
            }
            int row1 = row0 + 8;
            if (row1 < M){
                vx = acc[i][j][2] + bx; vy = acc[i][j][3] + by;
                if (relu){ vx = fmaxf(vx, 0.f); vy = fmaxf(vy, 0.f); }
                *reinterpret_cast<float2*>(Cm + (size_t)row1*matcols + c2) = make_float2(vx, vy);
            }
        }
    }
}

// ---------------- edge: alpha logits over CSR slots (4 slots per warp) --------
__global__ __launch_bounds__(256) void k_edge_alpha(
    const float* __restrict__ We, const float* __restrict__ be)
{
    __shared__ float sWe[4*HID];
    __shared__ float sbe[HID];
    int t = threadIdx.x;
    for (int i = t; i < 4*HID; i += 256) sWe[i] = We[i];
    if (t < HID) sbe[t] = be[t];
    __syncthreads();
    int warp = t >> 5, lane = t & 31;
    int hh = lane >> 3, o = lane & 7;
    int cb = hh*Dd + o;
#pragma unroll
    for (int i4 = 0; i4 < 4; i4++){
        int s = blockIdx.x*32 + warp + 8*i4;
        int src = g_srcs[s];
        int dst = g_dsts[s];
        float4 ej = g_eap[s];
        const float* qr = g_q + (size_t)dst*HID;
        const float* kr = g_k + (size_t)src*HID;
        float part = 0.f;
#pragma unroll
        for (int i = 0; i < 5; i++){
            int c = cb + 8*i;
            float ev = sbe[c] + ej.x*sWe[c] + ej.y*sWe[HID+c] + ej.z*sWe[2*HID+c] + ej.w*sWe[3*HID+c];
            part = fmaf(qr[c], kr[c] + ev, part);
        }
        part += __shfl_down_sync(0xffffffffu, part, 4, 8);
        part += __shfl_down_sync(0xffffffffu, part, 2, 8);
        part += __shfl_down_sync(0xffffffffu, part, 1, 8);
        if (o == 0)
            g_alpha[(size_t)s*4 + hh] = part * 0.15811388300841897f;
    }
}

// ---------------- per-node softmax (contiguous alpha) ----------------
__global__ __launch_bounds__(256) void k_node_soft(){
    int t = threadIdx.x, warp = t >> 5, lane = t & 31;
    int n = blockIdx.x*8 + warp;
    int beg = g_rowptr[n], end = g_rowptr[n+1];
    int deg = end - beg;
    if (deg == 0) return;
    float4* al4 = reinterpret_cast<float4*>(g_alpha);

    float m0=-3.4e38f, m1=-3.4e38f, m2=-3.4e38f, m3=-3.4e38f;
    for (int i = lane; i < deg; i += 32){
        float4 a = al4[beg + i];
        m0 = fmaxf(m0, a.x); m1 = fmaxf(m1, a.y);
        m2 = fmaxf(m2, a.z); m3 = fmaxf(m3, a.w);
    }
#pragma unroll
    for (int off = 16; off; off >>= 1){
        m0 = fmaxf(m0, __shfl_xor_sync(0xffffffffu, m0, off));
        m1 = fmaxf(m1, __shfl_xor_sync(0xffffffffu, m1, off));
        m2 = fmaxf(m2, __shfl_xor_sync(0xffffffffu, m2, off));
        m3 = fmaxf(m3, __shfl_xor_sync(0xffffffffu, m3, off));
    }
    float s0=0.f, s1=0.f, s2=0.f, s3=0.f;
    for (int i = lane; i < deg; i += 32){
        float4 a = al4[beg + i];
        a.x = expf(a.x - m0); a.y = expf(a.y - m1);
        a.z = expf(a.z - m2); a.w = expf(a.w - m3);
        s0 += a.x; s1 += a.y; s2 += a.z; s3 += a.w;
        al4[beg + i] = a;
    }
#pragma unroll
    for (int off = 16; off; off >>= 1){
        s0 += __shfl_xor_sync(0xffffffffu, s0, off);
        s1 += __shfl_xor_sync(0xffffffffu, s1, off);
        s2 += __shfl_xor_sync(0xffffffffu, s2, off);
        s3 += __shfl_xor_sync(0xffffffffu, s3, off);
    }
    float r0 = 1.f/s0, r1 = 1.f/s1, r2 = 1.f/s2, r3 = 1.f/s3;
    for (int i = lane; i < deg; i += 32){
        float4 a = al4[beg + i];
        a.x *= r0; a.y *= r1; a.z *= r2; a.w *= r3;
        al4[beg + i] = a;
    }
}

// ---------------- per-node aggregation (8 nodes per block, contiguous staging) -
#define ECH 64
#define NPB 8
__global__ __launch_bounds__(HID) void k_node_aggr(
    const float* __restrict__ We, const float* __restrict__ be)
{
    __shared__ float sWe[4*HID];
    __shared__ float sbe[HID];
    __shared__ float4 s_ea[ECH];
    __shared__ float4 s_a[ECH];
    __shared__ int    s_src[ECH];
    int c = threadIdx.x;
    for (int i = c; i < 4*HID; i += HID) sWe[i] = We[i];
    sbe[c] = be[c];
    int h = c / Dd;
    const float4* al4 = reinterpret_cast<const float4*>(g_alpha);

    for (int nn = 0; nn < NPB; nn++){
        int n = blockIdx.x*NPB + nn;
        int beg = g_rowptr[n], end = g_rowptr[n+1];
        float acc = 0.f;
        for (int base = beg; base < end; base += ECH){
            int m = min(ECH, end - base);
            __syncthreads();
            if (c < m){
                s_src[c] = g_srcs[base + c];
                s_ea[c]  = g_eap[base + c];
                s_a[c]   = al4[base + c];
            }
            __syncthreads();
            for (int j = 0; j < m; j++){
                float4 ej = s_ea[j];
                float w = reinterpret_cast<const float*>(&s_a[j])[h];
                float ev = sbe[c] + ej.x*sWe[c] + ej.y*sWe[HID+c]
                         + ej.z*sWe[2*HID+c] + ej.w*sWe[3*HID+c];
                acc = fmaf(g_v[(size_t)s_src[j]*HID + c] + ev, w, acc);
            }
        }
        g_out[(size_t)n*HID + c] = acc;
    }
}

// ---------------- beta gate + combine (writes f32 xc + rounded xct) ----------
__global__ __launch_bounds__(256) void k_beta(const float* __restrict__ Wb, int l){
    int t = threadIdx.x, warp = t >> 5, lane = t & 31;
    int n = blockIdx.x*8 + warp;
    const float* o = g_out  + (size_t)n*HID;
    const float* r = g_skip + (size_t)n*HID;
    float oc[5], rc[5];
    float p = 0.f;
#pragma unroll
    for (int i = 0; i < 5; i++){
        int c = lane + 32*i;
        oc[i] = o[c]; rc[i] = r[c];
        p += oc[i]*Wb[c] + rc[i]*Wb[HID+c] + (oc[i]-rc[i])*Wb[2*HID+c];
    }
#pragma unroll
    for (int off = 16; off; off >>= 1) p += __shfl_xor_sync(0xffffffffu, p, off);
    float beta = 1.f/(1.f + expf(-p));
    float* hx  = g_xc  + (size_t)n*JK + (size_t)l*HID;
    float* hxt = g_xct + (size_t)n*JK + (size_t)l*HID;
#pragma unroll
    for (int i = 0; i < 5; i++){
        int c = lane + 32*i;
        float v = beta*rc[i] + (1.f - beta)*oc[i];
        hx[c]  = v;
        hxt[c] = rna_tf32(v);
    }
}

// ---------------- pooling ----------------
__global__ void k_init_pool(){
    int idx = blockIdx.x*blockDim.x + threadIdx.x;
    if (idx < Gg){ g_gmax[idx] = 0u; g_gden[idx] = 0.f; }
    if (idx < Gg*JK) g_pooled[idx] = 0.f;
}

__global__ __launch_bounds__(256) void k_gate(const float* __restrict__ Wg2,
                                              const float* __restrict__ bg2){
    int t = threadIdx.x, warp = t >> 5, lane = t & 31;
    int n = blockIdx.x*8 + warp;
    const float* tp = g_out + (size_t)n*HID;
    float p = 0.f;
#pragma unroll
    for (int i = 0; i < 5; i++){
        int c = lane + 32*i;
        p = fmaf(tp[c], Wg2[c], p);
    }
#pragma unroll
    for (int off = 16; off; off >>= 1) p += __shfl_xor_sync(0xffffffffu, p, off);
    if (lane == 0){
        float gate = p + bg2[0];
        g_gate[n] = gate;
        atomicMax(&g_gmax[g_batch32[n]], fenc(gate));
    }
}

__global__ void k_ge(){
    __shared__ float s[Gg];
    int t = threadIdx.x;
    if (t < Gg) s[t] = 0.f;
    __syncthreads();
    int n = blockIdx.x*blockDim.x + t;
    if (n < Nn){
        int b = g_batch32[n];
        float ge = expf(g_gate[n] - fdec(g_gmax[b]));
        g_gate[n] = ge;
        atomicAdd(&s[b], ge);
    }
    __syncthreads();
    if (t < Gg) atomicAdd(&g_gden[t], s[t]);
}

// pooled[g] += (ge[n]/gden[g]) * xc[n]  (att division fused in)
__global__ __launch_bounds__(JK) void k_pool(){
    int c = threadIdx.x;
    int n0 = blockIdx.x*128;
    if (n0 >= Nn) return;
    int nend = min(n0 + 128, Nn);
    int curg = g_batch32[n0];
    float rden = 1.f / g_gden[curg];
    float acc = 0.f;
    for (int n = n0; n < nend; n++){
        int g = g_batch32[n];
        if (g != curg){
            atomicAdd(&g_pooled[curg*JK + c], acc);
            acc = 0.f; curg = g;
            rden = 1.f / g_gden[curg];
        }
        acc = fmaf(g_gate[n]*rden, g_xc[(size_t)n*JK + c], acc);
    }
    atomicAdd(&g_pooled[curg*JK + c], acc);
}

__global__ __launch_bounds__(JK) void k_final(const float* __restrict__ Wh1,
                                              const float* __restrict__ bh1,
                                              const float* __restrict__ Wh2,
                                              const float* __restrict__ bh2,
                                              float* __restrict__ outp){
    __shared__ float p[JK];
    __shared__ float t1[JK];
    int g = blockIdx.x, c = threadIdx.x;
    p[c] = g_pooled[g*JK + c];
    __syncthreads();
    float acc = bh1[c];
    for (int k = 0; k < JK; k++) acc = fmaf(p[k], Wh1[k*JK + c], acc);
    t1[c] = fmaxf(acc, 0.f);
    __syncthreads();
    int warp = c >> 5, lane = c & 31;
    if (warp < 6){
        float s = 0.f;
        for (int k = lane; k < JK; k += 32) s = fmaf(t1[k], Wh2[k*6 + warp], s);
#pragma unroll
        for (int off = 16; off; off >>= 1) s += __shfl_xor_sync(0xffffffffu, s, off);
        if (lane == 0) outp[g*6 + warp] = s + bh2[warp];
    }
}

// ---------------- host ----------------
extern "C" void kernel_launch(void* const* d_in, const int* in_sizes, int n_in,
                              void* d_out, int out_size){
    const float* x     = (const float*)d_in[0];
    const void*  ei    = d_in[1];
    const float* ea    = (const float*)d_in[2];
    const void*  batch = d_in[3];
    const float* W_in  = (const float*)d_in[4];
    const float* b_in  = (const float*)d_in[5];
    const float* Wq    = (const float*)d_in[6];
    const float* bq    = (const float*)d_in[7];
    const float* Wk    = (const float*)d_in[8];
    const float* bk    = (const float*)d_in[9];
    const float* Wv    = (const float*)d_in[10];
    const float* bv    = (const float*)d_in[11];
    const float* We    = (const float*)d_in[12];
    const float* be    = (const float*)d_in[13];
    const float* Wskip = (const float*)d_in[14];
    const float* bskip = (const float*)d_in[15];
    const float* Wbeta = (const float*)d_in[16];
    const float* Wg1   = (const float*)d_in[17];
    const float* bg1   = (const float*)d_in[18];
    const float* Wg2   = (const float*)d_in[19];
    const float* bg2   = (const float*)d_in[20];
    const float* Wh1   = (const float*)d_in[21];
    const float* bh1   = (const float*)d_in[22];
    const float* Wh2   = (const float*)d_in[23];
    const float* bh2   = (const float*)d_in[24];
    float* outp = (float*)d_out;

    void *ph0, *pxct, *pout, *pq, *pk, *pv, *ps;
    void *pwq, *pwk, *pwv, *pws, *pwg1;
    cudaGetSymbolAddress(&ph0, g_h0);
    cudaGetSymbolAddress(&pxct, g_xct);
    cudaGetSymbolAddress(&pout, g_out);
    cudaGetSymbolAddress(&pq, g_q);
    cudaGetSymbolAddress(&pk, g_k);
    cudaGetSymbolAddress(&pv, g_v);
    cudaGetSymbolAddress(&ps, g_skip);
    cudaGetSymbolAddress(&pwq, g_wq);
    cudaGetSymbolAddress(&pwk, g_wk);
    cudaGetSymbolAddress(&pwv, g_wv);
    cudaGetSymbolAddress(&pws, g_ws);
    cudaGetSymbolAddress(&pwg1, g_wg1);
    float* h0  = (float*)ph0;
    float* xct = (float*)pxct;
    float* tmp = (float*)pout;
    float* qp  = (float*)pq;
    float* kp  = (float*)pk;
    float* vp  = (float*)pv;
    float* sp  = (float*)ps;
    float* wq  = (float*)pwq;
    float* wk  = (float*)pwk;
    float* wv  = (float*)pwv;
    float* ws  = (float*)pws;
    float* wg1 = (float*)pwg1;

    static int smem_set = 0;
    if (!smem_set){
        cudaFuncSetAttribute(k_gemm_tf32, cudaFuncAttributeMaxDynamicSharedMemorySize, SMEM_GEMM);
        smem_set = 1;
    }

    k_detect<<<1, 256>>>(ei);
    k_zero_cnt<<<(Nn + 255)/256, 256>>>();
    k_convert<<<(2*Ee + 255)/256, 256>>>(ei, batch);
    k_cvtw<<<(4*2*HID*HID + JK*HID + 255)/256, 256>>>(Wq, Wk, Wv, Wskip, Wg1);
    k_scan1<<<NBLK, 256>>>();
    k_scan2<<<1, 256>>>();
    k_scan3<<<NBLK, 256>>>();
    k_fill<<<(Ee + 255)/256, 256>>>(ea);

    k_input<<<Nn, HID>>>(x, W_in, b_in);

    for (int l = 0; l < 2; l++){
        const float* A = l ? xct : h0;
        int lda = l ? JK : HID;
        dim3 grid(5, (Nn + 127)/128);
        k_gemm_tf32<<<grid, 256, SMEM_GEMM>>>(A, lda, Nn, HID,
            wq + l*HID*HID, wk + l*HID*HID, wv + l*HID*HID, ws + l*HID*HID,
            bq + l*HID, bk + l*HID, bv + l*HID, bskip + l*HID,
            HID, 4*HID, qp, kp, vp, sp, 0);
        k_edge_alpha<<<Ee/32, 256>>>(We + l*4*HID, be + l*HID);
        k_node_soft<<<Nn/8, 256>>>();
        k_node_aggr<<<Nn/NPB, HID>>>(We + l*4*HID, be + l*HID);
        k_beta<<<Nn/8, 256>>>(Wbeta + l*3*HID, l);
    }

    {
        dim3 grid(2, (Nn + 127)/128);
        k_gemm_tf32<<<grid, 256, SMEM_GEMM>>>(xct, JK, Nn, JK,
            wg1, wg1, wg1, wg1, bg1, bg1, bg1, bg1,
            HID, HID, tmp, tmp, tmp, tmp, 1);
    }
    k_init_pool<<<40, 256>>>();
    k_gate<<<Nn/8, 256>>>(Wg2, bg2);
    k_ge<<<(Nn + 255)/256, 256>>>();
    k_pool<<<(Nn + 127)/128, JK>>>();
    k_final<<<Gg, JK>>>(Wh1, bh1, Wh2, bh2, outp);
}